// round 14
// baseline (speedup 1.0000x reference)
#include <cuda_runtime.h>
#include <cuda_bf16.h>
#include <math.h>
#include <stdint.h>

// Problem constants
#define BB     2
#define NN     1024
#define DIMM   1024
#define DEPTH  4
#define HEADS  16
#define DHEAD  64
#define INNER  1024
#define MLPD   4096
#define TOK    (BB*NN)       // 2048

typedef __nv_bfloat16 bf16;

// ---------------------------------------------------------------------------
// Scratch (no cudaMalloc allowed)
// ---------------------------------------------------------------------------
__device__ float g_part[4 * TOK * DIMM];

__device__ bf16 g_qkvh[TOK * 3 * INNER], g_qkvl[TOK * 3 * INNER];
__device__ bf16 g_hh [TOK * DIMM],  g_hl [TOK * DIMM];
__device__ bf16 g_h2h[TOK * MLPD],  g_h2l[TOK * MLPD];
__device__ bf16 g_oh [TOK * INNER], g_ol [TOK * INNER];

__device__ bf16 g_wqkv_h[DEPTH * DIMM * 3 * INNER], g_wqkv_l[DEPTH * DIMM * 3 * INNER];
__device__ bf16 g_wout_h[DEPTH * INNER * DIMM],     g_wout_l[DEPTH * INNER * DIMM];
__device__ bf16 g_wff1_h[DEPTH * DIMM * MLPD],      g_wff1_l[DEPTH * DIMM * MLPD];
__device__ bf16 g_wff2_h[DEPTH * MLPD * DIMM],      g_wff2_l[DEPTH * MLPD * DIMM];

// ---------------------------------------------------------------------------
// Helpers
// ---------------------------------------------------------------------------
__device__ __forceinline__ uint32_t s2u(const void* p) {
    uint32_t a;
    asm("{ .reg .u64 t; cvta.to.shared.u64 t, %1; cvt.u32.u64 %0, t; }"
        : "=r"(a) : "l"(p));
    return a;
}

__device__ __forceinline__ void split1(float x, bf16& h, bf16& l) {
    h = __float2bfloat16(x);
    l = __float2bfloat16(x - __bfloat162float(h));
}

#define LDX4(r, addr) \
    asm volatile("ldmatrix.sync.aligned.m8n8.x4.shared.b16 {%0,%1,%2,%3}, [%4];" \
        : "=r"((r)[0]), "=r"((r)[1]), "=r"((r)[2]), "=r"((r)[3]) : "r"(addr))

#define LDX4T(r, addr) \
    asm volatile("ldmatrix.sync.aligned.m8n8.x4.trans.shared.b16 {%0,%1,%2,%3}, [%4];" \
        : "=r"((r)[0]), "=r"((r)[1]), "=r"((r)[2]), "=r"((r)[3]) : "r"(addr))

#define MMA(cd, a, b) \
    asm volatile("mma.sync.aligned.m16n8k16.row.col.f32.bf16.bf16.f32 " \
        "{%0,%1,%2,%3}, {%4,%5,%6,%7}, {%8,%9}, {%0,%1,%2,%3};" \
        : "+f"((cd)[0]), "+f"((cd)[1]), "+f"((cd)[2]), "+f"((cd)[3]) \
        : "r"((a)[0]), "r"((a)[1]), "r"((a)[2]), "r"((a)[3]), \
          "r"((b)[0]), "r"((b)[1]))

#define CP16(dst, src) \
    asm volatile("cp.async.cg.shared.global [%0], [%1], 16;" \
        :: "r"(dst), "l"(src) : "memory")

__device__ __forceinline__ float gelu1(float v) {
    return 0.5f * v * (1.f + erff(v * 0.70710678118654752f));
}

// ---------------------------------------------------------------------------
// fp32 -> bf16 hi/lo elementwise convert
// ---------------------------------------------------------------------------
__global__ void cvt_kernel(const float* __restrict__ in,
                           bf16* __restrict__ h, bf16* __restrict__ l, int n4)
{
    for (int i = blockIdx.x * blockDim.x + threadIdx.x; i < n4;
         i += gridDim.x * blockDim.x) {
        float4 v = ((const float4*)in)[i];
        bf16 h0, l0, h1, l1, h2, l2, h3, l3;
        split1(v.x, h0, l0); split1(v.y, h1, l1);
        split1(v.z, h2, l2); split1(v.w, h3, l3);
        __nv_bfloat162 hp0 = __halves2bfloat162(h0, h1);
        __nv_bfloat162 hp1 = __halves2bfloat162(h2, h3);
        __nv_bfloat162 lp0 = __halves2bfloat162(l0, l1);
        __nv_bfloat162 lp1 = __halves2bfloat162(l2, l3);
        ((uint2*)h)[i] = make_uint2(*(uint32_t*)&hp0, *(uint32_t*)&hp1);
        ((uint2*)l)[i] = make_uint2(*(uint32_t*)&lp0, *(uint32_t*)&lp1);
    }
}

// ---------------------------------------------------------------------------
// Split-K reduce: x[i] += bias[col] + sum_p part[p][i]
// ---------------------------------------------------------------------------
template <int NP>
__global__ void reduce_kernel(float* __restrict__ x,
                              const float* __restrict__ bias,
                              const float* __restrict__ part, int n4)
{
    int i = blockIdx.x * blockDim.x + threadIdx.x;
    if (i >= n4) return;
    float4 v = ((const float4*)x)[i];
    float4 b = ((const float4*)bias)[i & (DIMM / 4 - 1)];
    v.x += b.x; v.y += b.y; v.z += b.z; v.w += b.w;
#pragma unroll
    for (int p = 0; p < NP; ++p) {
        float4 pv = ((const float4*)(part + (size_t)p * TOK * DIMM))[i];
        v.x += pv.x; v.y += pv.y; v.z += pv.z; v.w += pv.w;
    }
    ((float4*)x)[i] = v;
}

// ---------------------------------------------------------------------------
// Tensor-core GEMM, bf16 hi/lo, 3-term split MMA, fp32 accumulate.
// CTA tile 256x128, 8 warps of 64x64 (4 m-groups x 2 n-groups), 256 threads,
// K-chunk 32 (2x k16), 2-stage cp.async ring. 1 CTA/SM (regs up to 255).
// EPI: 0 plain fp32, 2 +bias+GELU -> bf16 h/l, 3 plain -> bf16 h/l
// ---------------------------------------------------------------------------
#define APITCH 40
#define BPITCH 136
#define AH_OFF 0
#define AL_OFF (256 * APITCH * 2)                // 20480
#define BH_OFF (2 * 256 * APITCH * 2)            // 40960
#define BL_OFF (BH_OFF + 32 * BPITCH * 2)        // 49664
#define STG_TOTAL (BL_OFF + 32 * BPITCH * 2)     // 58368
#define GEMM_SMEM (2 * STG_TOTAL)                // 116736

template <int EPI>
__global__ __launch_bounds__(256)
void mma_gemm(const bf16* __restrict__ Ah, const bf16* __restrict__ Al,
              const bf16* __restrict__ Bh, const bf16* __restrict__ Bl,
              float* __restrict__ C, const float* __restrict__ bias,
              bf16* __restrict__ Ch, bf16* __restrict__ Cl,
              int M, int Ncols, int lda, int Kpart)
{
    extern __shared__ __align__(16) char smem[];
    const uint32_t sbase = s2u(smem);

    const int tid = threadIdx.x, lane = tid & 31, wid = tid >> 5;
    const int m0 = blockIdx.y * 256, n0 = blockIdx.x * 128;
    const int wm = (wid & 3) * 64, wn = (wid >> 2) * 64;
    const int koff = blockIdx.z * Kpart;
    C += (size_t)blockIdx.z * M * Ncols;

    float acc[4][8][4];
#pragma unroll
    for (int i = 0; i < 4; ++i)
#pragma unroll
        for (int j = 0; j < 8; ++j)
#pragma unroll
            for (int q = 0; q < 4; ++q) acc[i][j][q] = 0.f;

    // ldmatrix per-lane byte offsets (relative to stage base)
    const uint32_t a_off = ((wm + (lane & 15)) * APITCH + (lane >> 4) * 8) * 2;
    const uint32_t b_off = ((lane & 15) * BPITCH + wn + (lane >> 4) * 8) * 2;

    const int NCH = Kpart / 32;

    // issue loads for chunk cc into stage buffer at byte offset so
    auto issue = [&](int cc, uint32_t so) {
#pragma unroll
        for (int i = 0; i < 4; ++i) {
            int idx = tid + i * 256;               // 0..1023
            int arow = idx >> 2, akc = (idx & 3) * 8;
            CP16(sbase + so + AH_OFF + (arow * APITCH + akc) * 2,
                 Ah + (size_t)(m0 + arow) * lda + koff + cc * 32 + akc);
            CP16(sbase + so + AL_OFF + (arow * APITCH + akc) * 2,
                 Al + (size_t)(m0 + arow) * lda + koff + cc * 32 + akc);
        }
#pragma unroll
        for (int i = 0; i < 2; ++i) {
            int idx = tid + i * 256;               // 0..511
            int bkr = idx >> 4, bn = (idx & 15) * 8;
            CP16(sbase + so + BH_OFF + (bkr * BPITCH + bn) * 2,
                 Bh + (size_t)(koff + cc * 32 + bkr) * Ncols + n0 + bn);
            CP16(sbase + so + BL_OFF + (bkr * BPITCH + bn) * 2,
                 Bl + (size_t)(koff + cc * 32 + bkr) * Ncols + n0 + bn);
        }
        asm volatile("cp.async.commit_group;" ::: "memory");
    };

    issue(0, 0);

    for (int c = 0; c < NCH; ++c) {
        const uint32_t so = (uint32_t)(c & 1) * STG_TOTAL;
        __syncthreads();                          // drain reads of other buffer
        if (c + 1 < NCH) {
            issue(c + 1, (uint32_t)((c + 1) & 1) * STG_TOTAL);
            asm volatile("cp.async.wait_group 1;" ::: "memory");
        } else {
            asm volatile("cp.async.wait_group 0;" ::: "memory");
        }
        __syncthreads();                          // chunk c visible

#pragma unroll
        for (int ks = 0; ks < 2; ++ks) {
            uint32_t bh[16], bl[16];
            {
                uint32_t bb = sbase + so + BH_OFF + b_off + ks * 16 * BPITCH * 2;
                uint32_t lb = sbase + so + BL_OFF + b_off + ks * 16 * BPITCH * 2;
#pragma unroll
                for (int j = 0; j < 4; ++j) {
                    LDX4T(bh + 4 * j, bb + 32 * j);
                    LDX4T(bl + 4 * j, lb + 32 * j);
                }
            }
            const uint32_t abase = sbase + so + AH_OFF + a_off + ks * 32;
            const uint32_t lbase = sbase + so + AL_OFF + a_off + ks * 32;
#pragma unroll
            for (int mi = 0; mi < 4; ++mi) {
                uint32_t ah[4], al[4];
                LDX4(ah, abase + mi * 16 * APITCH * 2);
                LDX4(al, lbase + mi * 16 * APITCH * 2);
                // same-acc reuse distance = 8 MMAs
#pragma unroll
                for (int ni = 0; ni < 8; ++ni) MMA(acc[mi][ni], ah, bh + ni * 2);
#pragma unroll
                for (int ni = 0; ni < 8; ++ni) MMA(acc[mi][ni], ah, bl + ni * 2);
#pragma unroll
                for (int ni = 0; ni < 8; ++ni) MMA(acc[mi][ni], al, bh + ni * 2);
            }
        }
    }

    // epilogue
#pragma unroll
    for (int mi = 0; mi < 4; ++mi) {
        int row = m0 + wm + mi * 16 + (lane >> 2);
#pragma unroll
        for (int ni = 0; ni < 8; ++ni) {
            int col = n0 + wn + ni * 8 + (lane & 3) * 2;
#pragma unroll
            for (int half = 0; half < 2; ++half) {
                int r = row + half * 8;
                float v0 = acc[mi][ni][half * 2 + 0];
                float v1 = acc[mi][ni][half * 2 + 1];
                size_t idx = (size_t)r * Ncols + col;
                if (EPI == 0) {
                    *(float2*)(C + idx) = make_float2(v0, v1);
                } else {
                    if (EPI == 2) {
                        v0 = gelu1(v0 + bias[col]);
                        v1 = gelu1(v1 + bias[col + 1]);
                    }
                    bf16 h0, l0, h1, l1;
                    split1(v0, h0, l0);
                    split1(v1, h1, l1);
                    __nv_bfloat162 hp = __halves2bfloat162(h0, h1);
                    __nv_bfloat162 lp = __halves2bfloat162(l0, l1);
                    *(uint32_t*)(Ch + idx) = *(uint32_t*)&hp;
                    *(uint32_t*)(Cl + idx) = *(uint32_t*)&lp;
                }
            }
        }
    }
}

// ---------------------------------------------------------------------------
// LayerNorm
// ---------------------------------------------------------------------------
__global__ void ln_kernel(const float* __restrict__ x,
                          const float* __restrict__ g,
                          const float* __restrict__ b,
                          bf16* __restrict__ oh, bf16* __restrict__ ol)
{
    int row = blockIdx.x;
    int tid = threadIdx.x;
    int lane = tid & 31, wid = tid >> 5;
    __shared__ float red[8];
    __shared__ float bc[2];

    float4 v = *(const float4*)(x + (size_t)row * DIMM + tid * 4);

    float s = v.x + v.y + v.z + v.w;
#pragma unroll
    for (int o = 16; o > 0; o >>= 1) s += __shfl_xor_sync(~0u, s, o);
    if (lane == 0) red[wid] = s;
    __syncthreads();
    if (tid == 0) {
        float t = 0.f;
#pragma unroll
        for (int i = 0; i < 8; ++i) t += red[i];
        bc[0] = t * (1.f / DIMM);
    }
    __syncthreads();
    float mu = bc[0];

    float dx = v.x - mu, dy = v.y - mu, dz = v.z - mu, dw = v.w - mu;
    float s2 = dx * dx + dy * dy + dz * dz + dw * dw;
#pragma unroll
    for (int o = 16; o > 0; o >>= 1) s2 += __shfl_xor_sync(~0u, s2, o);
    if (lane == 0) red[wid] = s2;
    __syncthreads();
    if (tid == 0) {
        float t = 0.f;
#pragma unroll
        for (int i = 0; i < 8; ++i) t += red[i];
        bc[1] = rsqrtf(t * (1.f / DIMM) + 1e-5f);
    }
    __syncthreads();
    float rstd = bc[1];

    float4 gg = *(const float4*)(g + tid * 4);
    float4 bb = *(const float4*)(b + tid * 4);
    float o0 = dx * rstd * gg.x + bb.x;
    float o1 = dy * rstd * gg.y + bb.y;
    float o2 = dz * rstd * gg.z + bb.z;
    float o3 = dw * rstd * gg.w + bb.w;

    bf16 h0, l0, h1, l1, h2, l2, h3, l3;
    split1(o0, h0, l0); split1(o1, h1, l1);
    split1(o2, h2, l2); split1(o3, h3, l3);
    __nv_bfloat162 hp0 = __halves2bfloat162(h0, h1);
    __nv_bfloat162 hp1 = __halves2bfloat162(h2, h3);
    __nv_bfloat162 lp0 = __halves2bfloat162(l0, l1);
    __nv_bfloat162 lp1 = __halves2bfloat162(l2, l3);
    size_t idx = (size_t)row * DIMM + tid * 4;
    *(uint2*)(oh + idx) = make_uint2(*(uint32_t*)&hp0, *(uint32_t*)&hp1);
    *(uint2*)(ol + idx) = make_uint2(*(uint32_t*)&lp0, *(uint32_t*)&lp1);
}

// ---------------------------------------------------------------------------
// MMA-based fused attention (unchanged from R12).
// ---------------------------------------------------------------------------
#define ATP 72
#define SPITCH 68
#define AQH 0
#define AQL (AQH + 64 * ATP * 2)
#define AKH (AQL + 64 * ATP * 2)
#define AKL (AKH + 64 * ATP * 2)
#define AVH (AKL + 64 * ATP * 2)
#define AVL (AVH + 64 * ATP * 2)
#define APH (AVL + 64 * ATP * 2)
#define APL (APH + 64 * ATP * 2)
#define ASS (APL + 64 * ATP * 2)
#define ASTAT (ASS + 64 * SPITCH * 4)
#define ATT_SMEM (ASTAT + 3 * 64 * 4)

__global__ __launch_bounds__(256, 2)
void attn_kernel(const bf16* __restrict__ qkvh, const bf16* __restrict__ qkvl,
                 const int* __restrict__ mask,
                 bf16* __restrict__ oh, bf16* __restrict__ ol)
{
    extern __shared__ __align__(16) char sm[];
    const uint32_t sb = s2u(sm);
    float* Ss     = (float*)(sm + ASS);
    float* m_s    = (float*)(sm + ASTAT);
    float* l_s    = m_s + 64;
    float* corr_s = l_s + 64;

    const int tid = threadIdx.x, lane = tid & 31, wid = tid >> 5;
    const int bh_i = blockIdx.y, b = bh_i >> 4, h = bh_i & 15;
    const int q0 = blockIdx.x * 64;
    const int wr = (wid & 3) * 16, wc = (wid >> 2) * 32;
    const float scale = 0.125f;
    const size_t rs = 3 * INNER;

    {
        const bf16* qh_g = qkvh + ((size_t)(b * NN + q0)) * rs + h * DHEAD;
        const bf16* ql_g = qkvl + ((size_t)(b * NN + q0)) * rs + h * DHEAD;
        for (int idx = tid; idx < 512; idx += 256) {
            int r = idx >> 3, ch = (idx & 7) * 8;
            size_t off = (size_t)r * rs + ch;
            *(uint4*)(sm + AQH + (r * ATP + ch) * 2) = *(const uint4*)(qh_g + off);
            *(uint4*)(sm + AQL + (r * ATP + ch) * 2) = *(const uint4*)(ql_g + off);
        }
    }
    if (tid < 64) { m_s[tid] = -INFINITY; l_s[tid] = 0.f; }

    float oacc[4][4];
#pragma unroll
    for (int i = 0; i < 4; ++i)
#pragma unroll
        for (int j = 0; j < 4; ++j) oacc[i][j] = 0.f;

    const uint32_t frag_a = ((lane & 15) * ATP + (lane >> 4) * 8) * 2;
    const uint32_t qa  = sb + AQH + wr * ATP * 2 + frag_a;
    const uint32_t qla = sb + AQL + wr * ATP * 2 + frag_a;
    const uint32_t ka  = sb + AKH + wc * ATP * 2 + frag_a;
    const uint32_t kla = sb + AKL + wc * ATP * 2 + frag_a;
    const uint32_t pa  = sb + APH + wr * ATP * 2 + frag_a;
    const uint32_t pla = sb + APL + wr * ATP * 2 + frag_a;
    const uint32_t va  = sb + AVH + ((lane & 15) * ATP + wc + (lane >> 4) * 8) * 2;
    const uint32_t vla = sb + AVL + ((lane & 15) * ATP + wc + (lane >> 4) * 8) * 2;

    for (int kt = 0; kt < NN / 64; ++kt) {
        const int k0 = kt * 64;
        __syncthreads();

        {
            const bf16* kh_g = qkvh + ((size_t)(b * NN + k0)) * rs + INNER + h * DHEAD;
            const bf16* kl_g = qkvl + ((size_t)(b * NN + k0)) * rs + INNER + h * DHEAD;
            for (int idx = tid; idx < 512; idx += 256) {
                int r = idx >> 3, ch = (idx & 7) * 8;
                size_t off = (size_t)r * rs + ch;
                *(uint4*)(sm + AKH + (r * ATP + ch) * 2) = *(const uint4*)(kh_g + off);
                *(uint4*)(sm + AKL + (r * ATP + ch) * 2) = *(const uint4*)(kl_g + off);
                *(uint4*)(sm + AVH + (r * ATP + ch) * 2) = *(const uint4*)(kh_g + INNER + off);
                *(uint4*)(sm + AVL + (r * ATP + ch) * 2) = *(const uint4*)(kl_g + INNER + off);
            }
        }
        __syncthreads();

        float sacc[4][4];
#pragma unroll
        for (int i = 0; i < 4; ++i)
#pragma unroll
            for (int j = 0; j < 4; ++j) sacc[i][j] = 0.f;

#pragma unroll
        for (int kd = 0; kd < 4; ++kd) {
            uint32_t aqh[4], aql[4];
            LDX4(aqh, qa + kd * 32);
            LDX4(aql, qla + kd * 32);
            uint32_t t0[4], t1[4], kh[8], kl[8];
            LDX4(t0, ka + kd * 32);
            LDX4(t1, ka + 16 * ATP * 2 + kd * 32);
            kh[0] = t0[0]; kh[1] = t0[2]; kh[2] = t0[1]; kh[3] = t0[3];
            kh[4] = t1[0]; kh[5] = t1[2]; kh[6] = t1[1]; kh[7] = t1[3];
            LDX4(t0, kla + kd * 32);
            LDX4(t1, kla + 16 * ATP * 2 + kd * 32);
            kl[0] = t0[0]; kl[1] = t0[2]; kl[2] = t0[1]; kl[3] = t0[3];
            kl[4] = t1[0]; kl[5] = t1[2]; kl[6] = t1[1]; kl[7] = t1[3];
#pragma unroll
            for (int nt = 0; nt < 4; ++nt) MMA(sacc[nt], aqh, kh + nt * 2);
#pragma unroll
            for (int nt = 0; nt < 4; ++nt) MMA(sacc[nt], aqh, kl + nt * 2);
#pragma unroll
            for (int nt = 0; nt < 4; ++nt) MMA(sacc[nt], aql, kh + nt * 2);
        }

        {
            const int* mbase = mask + ((size_t)b * NN + q0) * NN + k0;
            int r0 = wr + (lane >> 2), r1 = r0 + 8;
#pragma unroll
            for (int nt = 0; nt < 4; ++nt) {
                int col = wc + nt * 8 + (lane & 3) * 2;
                const int* m0p = mbase + (size_t)r0 * NN + col;
                const int* m1p = mbase + (size_t)r1 * NN + col;
                Ss[r0 * SPITCH + col]     = m0p[0] ? sacc[nt][0] * scale : -1e9f;
                Ss[r0 * SPITCH + col + 1] = m0p[1] ? sacc[nt][1] * scale : -1e9f;
                Ss[r1 * SPITCH + col]     = m1p[0] ? sacc[nt][2] * scale : -1e9f;
                Ss[r1 * SPITCH + col + 1] = m1p[1] ? sacc[nt][3] * scale : -1e9f;
            }
        }
        __syncthreads();

        {
            int r = tid >> 2, q = tid & 3;
            float* row = &Ss[r * SPITCH + q * 16];
            float mx = m_s[r];
            float tmax = -INFINITY;
#pragma unroll
            for (int j = 0; j < 16; ++j) tmax = fmaxf(tmax, row[j]);
            tmax = fmaxf(tmax, __shfl_xor_sync(~0u, tmax, 1));
            tmax = fmaxf(tmax, __shfl_xor_sync(~0u, tmax, 2));
            float nm = fmaxf(mx, tmax);
            float sum = 0.f;
#pragma unroll
            for (int j = 0; j < 16; ++j) {
                float p = __expf(row[j] - nm);
                row[j] = p;
                sum += p;
            }
            sum += __shfl_xor_sync(~0u, sum, 1);
            sum += __shfl_xor_sync(~0u, sum, 2);
            if (q == 0) {
                float corr = __expf(mx - nm);
                m_s[r] = nm;
                l_s[r] = l_s[r] * corr + sum;
                corr_s[r] = corr;
            }
        }
        __syncthreads();

        for (int idx = tid; idx < 512; idx += 256) {
            int r = idx >> 3, ch = (idx & 7) * 8;
            float4 p0 = *(float4*)&Ss[r * SPITCH + ch];
            float4 p1 = *(float4*)&Ss[r * SPITCH + ch + 4];
            bf16 h0, l0, h1, l1, h2, l2, h3, l3, h4, l4, h5, l5, h6, l6, h7, l7;
            split1(p0.x, h0, l0); split1(p0.y, h1, l1);
            split1(p0.z, h2, l2); split1(p0.w, h3, l3);
            split1(p1.x, h4, l4); split1(p1.y, h5, l5);
            split1(p1.z, h6, l6); split1(p1.w, h7, l7);
            __nv_bfloat162 a0 = __halves2bfloat162(h0, h1), a1 = __halves2bfloat162(h2, h3);
            __nv_bfloat162 a2 = __halves2bfloat162(h4, h5), a3 = __halves2bfloat162(h6, h7);
            __nv_bfloat162 c0 = __halves2bfloat162(l0, l1), c1 = __halves2bfloat162(l2, l3);
            __nv_bfloat162 c2 = __halves2bfloat162(l4, l5), c3 = __halves2bfloat162(l6, l7);
            *(uint4*)(sm + APH + (r * ATP + ch) * 2) =
                make_uint4(*(uint32_t*)&a0, *(uint32_t*)&a1, *(uint32_t*)&a2, *(uint32_t*)&a3);
            *(uint4*)(sm + APL + (r * ATP + ch) * 2) =
                make_uint4(*(uint32_t*)&c0, *(uint32_t*)&c1, *(uint32_t*)&c2, *(uint32_t*)&c3);
        }
        __syncthreads();

        {
            float c0 = corr_s[wr + (lane >> 2)];
            float c1 = corr_s[wr + (lane >> 2) + 8];
#pragma unroll
            for (int nt = 0; nt < 4; ++nt) {
                oacc[nt][0] *= c0; oacc[nt][1] *= c0;
                oacc[nt][2] *= c1; oacc[nt][3] *= c1;
            }
        }
#pragma unroll
        for (int kd = 0; kd < 4; ++kd) {
            uint32_t ap[4], apl[4];
            LDX4(ap,  pa  + kd * 32);
            LDX4(apl, pla + kd * 32);
            uint32_t vh[8], vl[8];
            LDX4T(vh + 0, va  + kd * (16 * ATP * 2));
            LDX4T(vh + 4, va  + kd * (16 * ATP * 2) + 32);
            LDX4T(vl + 0, vla + kd * (16 * ATP * 2));
            LDX4T(vl + 4, vla + kd * (16 * ATP * 2) + 32);
#pragma unroll
            for (int nt = 0; nt < 4; ++nt) MMA(oacc[nt], ap,  vh + nt * 2);
#pragma unroll
            for (int nt = 0; nt < 4; ++nt) MMA(oacc[nt], ap,  vl + nt * 2);
#pragma unroll
            for (int nt = 0; nt < 4; ++nt) MMA(oacc[nt], apl, vh + nt * 2);
        }
    }

    {
        int r0 = wr + (lane >> 2), r1 = r0 + 8;
        float il0 = 1.f / l_s[r0];
        float il1 = 1.f / l_s[r1];
        size_t base0 = ((size_t)(b * NN + q0 + r0)) * INNER + h * DHEAD;
        size_t base1 = ((size_t)(b * NN + q0 + r1)) * INNER + h * DHEAD;
#pragma unroll
        for (int nt = 0; nt < 4; ++nt) {
            int col = wc + nt * 8 + (lane & 3) * 2;
            float v0 = oacc[nt][0] * il0, v1 = oacc[nt][1] * il0;
            float v2 = oacc[nt][2] * il1, v3 = oacc[nt][3] * il1;
            bf16 h0, l0, h1, l1;
            split1(v0, h0, l0); split1(v1, h1, l1);
            __nv_bfloat162 hp = __halves2bfloat162(h0, h1);
            __nv_bfloat162 lp = __halves2bfloat162(l0, l1);
            *(uint32_t*)(oh + base0 + col) = *(uint32_t*)&hp;
            *(uint32_t*)(ol + base0 + col) = *(uint32_t*)&lp;
            split1(v2, h0, l0); split1(v3, h1, l1);
            hp = __halves2bfloat162(h0, h1);
            lp = __halves2bfloat162(l0, l1);
            *(uint32_t*)(oh + base1 + col) = *(uint32_t*)&hp;
            *(uint32_t*)(ol + base1 + col) = *(uint32_t*)&lp;
        }
    }
}

// ---------------------------------------------------------------------------
// Launch
// ---------------------------------------------------------------------------
extern "C" void kernel_launch(void* const* d_in, const int* in_sizes, int n_in,
                              void* d_out, int out_size)
{
    const float* x_in  = (const float*)d_in[0];
    const int*   mask  = (const int*)  d_in[1];
    const float* ln1_g = (const float*)d_in[2];
    const float* ln1_b = (const float*)d_in[3];
    const float* qkv_w = (const float*)d_in[4];
    const float* out_w = (const float*)d_in[5];
    const float* out_b = (const float*)d_in[6];
    const float* ln2_g = (const float*)d_in[7];
    const float* ln2_b = (const float*)d_in[8];
    const float* ff1_w = (const float*)d_in[9];
    const float* ff1_b = (const float*)d_in[10];
    const float* ff2_w = (const float*)d_in[11];
    const float* ff2_b = (const float*)d_in[12];
    float* x = (float*)d_out;

    float* part;
    bf16 *qkvh, *qkvl, *hh, *hl, *h2h, *h2l, *oh, *ol;
    bf16 *wqh, *wql, *woh, *wol, *wf1h, *wf1l, *wf2h, *wf2l;
    cudaGetSymbolAddress((void**)&part, g_part);
    cudaGetSymbolAddress((void**)&qkvh, g_qkvh); cudaGetSymbolAddress((void**)&qkvl, g_qkvl);
    cudaGetSymbolAddress((void**)&hh,  g_hh);  cudaGetSymbolAddress((void**)&hl,  g_hl);
    cudaGetSymbolAddress((void**)&h2h, g_h2h); cudaGetSymbolAddress((void**)&h2l, g_h2l);
    cudaGetSymbolAddress((void**)&oh,  g_oh);  cudaGetSymbolAddress((void**)&ol,  g_ol);
    cudaGetSymbolAddress((void**)&wqh, g_wqkv_h); cudaGetSymbolAddress((void**)&wql, g_wqkv_l);
    cudaGetSymbolAddress((void**)&woh, g_wout_h); cudaGetSymbolAddress((void**)&wol, g_wout_l);
    cudaGetSymbolAddress((void**)&wf1h, g_wff1_h); cudaGetSymbolAddress((void**)&wf1l, g_wff1_l);
    cudaGetSymbolAddress((void**)&wf2h, g_wff2_h); cudaGetSymbolAddress((void**)&wf2l, g_wff2_l);

    cudaFuncSetAttribute(attn_kernel,
                         cudaFuncAttributeMaxDynamicSharedMemorySize, ATT_SMEM);
    cudaFuncSetAttribute(mma_gemm<0>,
                         cudaFuncAttributeMaxDynamicSharedMemorySize, GEMM_SMEM);
    cudaFuncSetAttribute(mma_gemm<2>,
                         cudaFuncAttributeMaxDynamicSharedMemorySize, GEMM_SMEM);
    cudaFuncSetAttribute(mma_gemm<3>,
                         cudaFuncAttributeMaxDynamicSharedMemorySize, GEMM_SMEM);

    cvt_kernel<<<4096, 256>>>(qkv_w, wqh, wql, DEPTH * DIMM * 3 * INNER / 4);
    cvt_kernel<<<2048, 256>>>(out_w, woh, wol, DEPTH * INNER * DIMM / 4);
    cvt_kernel<<<4096, 256>>>(ff1_w, wf1h, wf1l, DEPTH * DIMM * MLPD / 4);
    cvt_kernel<<<4096, 256>>>(ff2_w, wf2h, wf2l, DEPTH * MLPD * DIMM / 4);

    cudaMemcpyAsync(x, x_in, sizeof(float) * (size_t)TOK * DIMM,
                    cudaMemcpyDeviceToDevice);

    const int RED_N4 = TOK * DIMM / 4;

    for (int l = 0; l < DEPTH; ++l) {
        size_t wq = (size_t)l * DIMM * 3 * INNER;
        size_t wo = (size_t)l * INNER * DIMM;
        size_t w1 = (size_t)l * DIMM * MLPD;
        size_t w2 = (size_t)l * MLPD * DIMM;

        ln_kernel<<<TOK, 256>>>(x, ln1_g + (size_t)l * DIMM,
                                   ln1_b + (size_t)l * DIMM, hh, hl);
        // qkv -> bf16 hi/lo directly (grid 24 x 8)
        mma_gemm<3><<<dim3(3 * INNER / 128, TOK / 256, 1), 256, GEMM_SMEM>>>(
            hh, hl, wqh + wq, wql + wq, nullptr, nullptr, qkvh, qkvl,
            TOK, 3 * INNER, DIMM, DIMM);
        attn_kernel<<<dim3(NN / 64, BB * HEADS), 256, ATT_SMEM>>>(
            qkvh, qkvl, mask, oh, ol);
        // out-proj: split-K 2 -> 8 x 8 x 2 = 128 CTAs (single wave)
        mma_gemm<0><<<dim3(DIMM / 128, TOK / 256, 2), 256, GEMM_SMEM>>>(
            oh, ol, woh + wo, wol + wo, part, nullptr, nullptr, nullptr,
            TOK, DIMM, INNER, INNER / 2);
        reduce_kernel<2><<<RED_N4 / 256, 256>>>(x, out_b + (size_t)l * DIMM,
                                                part, RED_N4);
        ln_kernel<<<TOK, 256>>>(x, ln2_g + (size_t)l * DIMM,
                                   ln2_b + (size_t)l * DIMM, hh, hl);
        // ff1 + GELU (grid 32 x 8)
        mma_gemm<2><<<dim3(MLPD / 128, TOK / 256, 1), 256, GEMM_SMEM>>>(
            hh, hl, wf1h + w1, wf1l + w1, nullptr, ff1_b + (size_t)l * MLPD,
            h2h, h2l, TOK, MLPD, DIMM, DIMM);
        // ff2: split-K 2 -> 8 x 8 x 2 = 128 CTAs (single wave), Kpart 2048
        mma_gemm<0><<<dim3(DIMM / 128, TOK / 256, 2), 256, GEMM_SMEM>>>(
            h2h, h2l, wf2h + w2, wf2l + w2, part, nullptr, nullptr, nullptr,
            TOK, DIMM, MLPD, MLPD / 2);
        reduce_kernel<2><<<RED_N4 / 256, 256>>>(x, ff2_b + (size_t)l * DIMM,
                                                part, RED_N4);
    }
}

// round 15
// speedup vs baseline: 1.1078x; 1.1078x over previous
#include <cuda_runtime.h>
#include <cuda_bf16.h>
#include <math.h>
#include <stdint.h>

// Problem constants
#define BB     2
#define NN     1024
#define DIMM   1024
#define DEPTH  4
#define HEADS  16
#define DHEAD  64
#define INNER  1024
#define MLPD   4096
#define TOK    (BB*NN)       // 2048

typedef __nv_bfloat16 bf16;

// ---------------------------------------------------------------------------
// Scratch (no cudaMalloc allowed)
// ---------------------------------------------------------------------------
__device__ float g_part[4 * TOK * DIMM];

__device__ bf16 g_qkvh[TOK * 3 * INNER], g_qkvl[TOK * 3 * INNER];
__device__ bf16 g_hh [TOK * DIMM],  g_hl [TOK * DIMM];
__device__ bf16 g_h2h[TOK * MLPD],  g_h2l[TOK * MLPD];
__device__ bf16 g_oh [TOK * INNER], g_ol [TOK * INNER];

__device__ bf16 g_wqkv_h[DEPTH * DIMM * 3 * INNER], g_wqkv_l[DEPTH * DIMM * 3 * INNER];
__device__ bf16 g_wout_h[DEPTH * INNER * DIMM],     g_wout_l[DEPTH * INNER * DIMM];
__device__ bf16 g_wff1_h[DEPTH * DIMM * MLPD],      g_wff1_l[DEPTH * DIMM * MLPD];
__device__ bf16 g_wff2_h[DEPTH * MLPD * DIMM],      g_wff2_l[DEPTH * MLPD * DIMM];

// ---------------------------------------------------------------------------
// Helpers
// ---------------------------------------------------------------------------
__device__ __forceinline__ uint32_t s2u(const void* p) {
    uint32_t a;
    asm("{ .reg .u64 t; cvta.to.shared.u64 t, %1; cvt.u32.u64 %0, t; }"
        : "=r"(a) : "l"(p));
    return a;
}

__device__ __forceinline__ void split1(float x, bf16& h, bf16& l) {
    h = __float2bfloat16(x);
    l = __float2bfloat16(x - __bfloat162float(h));
}

#define LDX4(r, addr) \
    asm volatile("ldmatrix.sync.aligned.m8n8.x4.shared.b16 {%0,%1,%2,%3}, [%4];" \
        : "=r"((r)[0]), "=r"((r)[1]), "=r"((r)[2]), "=r"((r)[3]) : "r"(addr))

#define LDX4T(r, addr) \
    asm volatile("ldmatrix.sync.aligned.m8n8.x4.trans.shared.b16 {%0,%1,%2,%3}, [%4];" \
        : "=r"((r)[0]), "=r"((r)[1]), "=r"((r)[2]), "=r"((r)[3]) : "r"(addr))

#define MMA(cd, a, b) \
    asm volatile("mma.sync.aligned.m16n8k16.row.col.f32.bf16.bf16.f32 " \
        "{%0,%1,%2,%3}, {%4,%5,%6,%7}, {%8,%9}, {%0,%1,%2,%3};" \
        : "+f"((cd)[0]), "+f"((cd)[1]), "+f"((cd)[2]), "+f"((cd)[3]) \
        : "r"((a)[0]), "r"((a)[1]), "r"((a)[2]), "r"((a)[3]), \
          "r"((b)[0]), "r"((b)[1]))

#define CP16(dst, src) \
    asm volatile("cp.async.cg.shared.global [%0], [%1], 16;" \
        :: "r"(dst), "l"(src) : "memory")

__device__ __forceinline__ float gelu1(float v) {
    return 0.5f * v * (1.f + erff(v * 0.70710678118654752f));
}

// ---------------------------------------------------------------------------
// fp32 -> bf16 hi/lo elementwise convert
// ---------------------------------------------------------------------------
__global__ void cvt_kernel(const float* __restrict__ in,
                           bf16* __restrict__ h, bf16* __restrict__ l, int n4)
{
    for (int i = blockIdx.x * blockDim.x + threadIdx.x; i < n4;
         i += gridDim.x * blockDim.x) {
        float4 v = ((const float4*)in)[i];
        bf16 h0, l0, h1, l1, h2, l2, h3, l3;
        split1(v.x, h0, l0); split1(v.y, h1, l1);
        split1(v.z, h2, l2); split1(v.w, h3, l3);
        __nv_bfloat162 hp0 = __halves2bfloat162(h0, h1);
        __nv_bfloat162 hp1 = __halves2bfloat162(h2, h3);
        __nv_bfloat162 lp0 = __halves2bfloat162(l0, l1);
        __nv_bfloat162 lp1 = __halves2bfloat162(l2, l3);
        ((uint2*)h)[i] = make_uint2(*(uint32_t*)&hp0, *(uint32_t*)&hp1);
        ((uint2*)l)[i] = make_uint2(*(uint32_t*)&lp0, *(uint32_t*)&lp1);
    }
}

// ---------------------------------------------------------------------------
// Split-K reduce (standalone, used only after the last layer's ff2):
// x[i] += bias[col] + sum_p part[p][i]
// ---------------------------------------------------------------------------
template <int NP>
__global__ void reduce_kernel(float* __restrict__ x,
                              const float* __restrict__ bias,
                              const float* __restrict__ part, int n4)
{
    int i = blockIdx.x * blockDim.x + threadIdx.x;
    if (i >= n4) return;
    float4 v = ((const float4*)x)[i];
    float4 b = ((const float4*)bias)[i & (DIMM / 4 - 1)];
    v.x += b.x; v.y += b.y; v.z += b.z; v.w += b.w;
#pragma unroll
    for (int p = 0; p < NP; ++p) {
        float4 pv = ((const float4*)(part + (size_t)p * TOK * DIMM))[i];
        v.x += pv.x; v.y += pv.y; v.z += pv.z; v.w += pv.w;
    }
    ((float4*)x)[i] = v;
}

// ---------------------------------------------------------------------------
// Fused split-K reduce + residual update + LayerNorm -> bf16 hi/lo.
// NP = 0: plain LN of x (no reduce).
// NP > 0: x += bias + sum(parts); write x; then LN(x) -> oh, ol.
// One block (256 thr) per token row.
// ---------------------------------------------------------------------------
template <int NP>
__global__ void red_ln_kernel(float* __restrict__ x,
                              const float* __restrict__ bias,
                              const float* __restrict__ part,
                              const float* __restrict__ g,
                              const float* __restrict__ b,
                              bf16* __restrict__ oh, bf16* __restrict__ ol)
{
    int row = blockIdx.x;
    int tid = threadIdx.x;
    int lane = tid & 31, wid = tid >> 5;
    __shared__ float red[8];
    __shared__ float bc[2];

    size_t i4 = (size_t)row * (DIMM / 4) + tid;
    float4 v = ((const float4*)x)[i4];

    if (NP > 0) {
        float4 bb = ((const float4*)bias)[tid];
        v.x += bb.x; v.y += bb.y; v.z += bb.z; v.w += bb.w;
#pragma unroll
        for (int p = 0; p < NP; ++p) {
            float4 pv = ((const float4*)(part + (size_t)p * TOK * DIMM))[i4];
            v.x += pv.x; v.y += pv.y; v.z += pv.z; v.w += pv.w;
        }
        ((float4*)x)[i4] = v;       // updated residual
    }

    float s = v.x + v.y + v.z + v.w;
#pragma unroll
    for (int o = 16; o > 0; o >>= 1) s += __shfl_xor_sync(~0u, s, o);
    if (lane == 0) red[wid] = s;
    __syncthreads();
    if (tid == 0) {
        float t = 0.f;
#pragma unroll
        for (int i = 0; i < 8; ++i) t += red[i];
        bc[0] = t * (1.f / DIMM);
    }
    __syncthreads();
    float mu = bc[0];

    float dx = v.x - mu, dy = v.y - mu, dz = v.z - mu, dw = v.w - mu;
    float s2 = dx * dx + dy * dy + dz * dz + dw * dw;
#pragma unroll
    for (int o = 16; o > 0; o >>= 1) s2 += __shfl_xor_sync(~0u, s2, o);
    if (lane == 0) red[wid] = s2;
    __syncthreads();
    if (tid == 0) {
        float t = 0.f;
#pragma unroll
        for (int i = 0; i < 8; ++i) t += red[i];
        bc[1] = rsqrtf(t * (1.f / DIMM) + 1e-5f);
    }
    __syncthreads();
    float rstd = bc[1];

    float4 gg = *(const float4*)(g + tid * 4);
    float4 bb2 = *(const float4*)(b + tid * 4);
    float o0 = dx * rstd * gg.x + bb2.x;
    float o1 = dy * rstd * gg.y + bb2.y;
    float o2 = dz * rstd * gg.z + bb2.z;
    float o3 = dw * rstd * gg.w + bb2.w;

    bf16 h0, l0, h1, l1, h2, l2, h3, l3;
    split1(o0, h0, l0); split1(o1, h1, l1);
    split1(o2, h2, l2); split1(o3, h3, l3);
    __nv_bfloat162 hp0 = __halves2bfloat162(h0, h1);
    __nv_bfloat162 hp1 = __halves2bfloat162(h2, h3);
    __nv_bfloat162 lp0 = __halves2bfloat162(l0, l1);
    __nv_bfloat162 lp1 = __halves2bfloat162(l2, l3);
    size_t idx = (size_t)row * DIMM + tid * 4;
    *(uint2*)(oh + idx) = make_uint2(*(uint32_t*)&hp0, *(uint32_t*)&hp1);
    *(uint2*)(ol + idx) = make_uint2(*(uint32_t*)&lp0, *(uint32_t*)&lp1);
}

// ---------------------------------------------------------------------------
// Tensor-core GEMM (R12 config): bf16 hi/lo, 3-term split MMA, fp32 accum.
// 128x128 tile/CTA, 256 threads (8 warps x 64x32), K-chunk 32 (2x k16),
// 2-stage cp.async ring.
// EPI: 0 plain fp32, 2 +bias+GELU -> bf16 h/l, 3 plain -> bf16 h/l
// ---------------------------------------------------------------------------
#define APITCH 40
#define BPITCH 136
#define AH_OFF 0
#define AL_OFF (128 * APITCH * 2)
#define BH_OFF (2 * 128 * APITCH * 2)
#define BL_OFF (BH_OFF + 32 * BPITCH * 2)
#define STG_TOTAL (BL_OFF + 32 * BPITCH * 2)     // 37888
#define GEMM_SMEM (2 * STG_TOTAL)                // 75776

template <int EPI>
__global__ __launch_bounds__(256, 2)
void mma_gemm(const bf16* __restrict__ Ah, const bf16* __restrict__ Al,
              const bf16* __restrict__ Bh, const bf16* __restrict__ Bl,
              float* __restrict__ C, const float* __restrict__ bias,
              bf16* __restrict__ Ch, bf16* __restrict__ Cl,
              int M, int Ncols, int lda, int Kpart)
{
    extern __shared__ __align__(16) char smem[];
    const uint32_t sbase = s2u(smem);

    const int tid = threadIdx.x, lane = tid & 31, wid = tid >> 5;
    const int m0 = blockIdx.y * 128, n0 = blockIdx.x * 128;
    const int wm = (wid >> 2) * 64, wn = (wid & 3) * 32;
    const int koff = blockIdx.z * Kpart;
    C += (size_t)blockIdx.z * M * Ncols;

    float acc[4][4][4];
#pragma unroll
    for (int i = 0; i < 4; ++i)
#pragma unroll
        for (int j = 0; j < 4; ++j)
#pragma unroll
            for (int q = 0; q < 4; ++q) acc[i][j][q] = 0.f;

    const uint32_t a_off = ((wm + (lane & 15)) * APITCH + (lane >> 4) * 8) * 2;
    const uint32_t b_off = ((lane & 15) * BPITCH + wn + (lane >> 4) * 8) * 2;

    const int NCH = Kpart / 32;

    auto issue = [&](int cc, uint32_t so) {
#pragma unroll
        for (int i = 0; i < 2; ++i) {
            int idx = tid + i * 256;
            int arow = idx >> 2, akc = (idx & 3) * 8;
            CP16(sbase + so + AH_OFF + (arow * APITCH + akc) * 2,
                 Ah + (size_t)(m0 + arow) * lda + koff + cc * 32 + akc);
            CP16(sbase + so + AL_OFF + (arow * APITCH + akc) * 2,
                 Al + (size_t)(m0 + arow) * lda + koff + cc * 32 + akc);
            int bkr = idx >> 4, bn = (idx & 15) * 8;
            CP16(sbase + so + BH_OFF + (bkr * BPITCH + bn) * 2,
                 Bh + (size_t)(koff + cc * 32 + bkr) * Ncols + n0 + bn);
            CP16(sbase + so + BL_OFF + (bkr * BPITCH + bn) * 2,
                 Bl + (size_t)(koff + cc * 32 + bkr) * Ncols + n0 + bn);
        }
        asm volatile("cp.async.commit_group;" ::: "memory");
    };

    issue(0, 0);

    for (int c = 0; c < NCH; ++c) {
        const uint32_t so = (uint32_t)(c & 1) * STG_TOTAL;
        __syncthreads();
        if (c + 1 < NCH) {
            issue(c + 1, (uint32_t)((c + 1) & 1) * STG_TOTAL);
            asm volatile("cp.async.wait_group 1;" ::: "memory");
        } else {
            asm volatile("cp.async.wait_group 0;" ::: "memory");
        }
        __syncthreads();

#pragma unroll
        for (int ks = 0; ks < 2; ++ks) {
            uint32_t bh[8], bl[8];
            {
                uint32_t bb = sbase + so + BH_OFF + b_off + ks * 16 * BPITCH * 2;
                uint32_t lb = sbase + so + BL_OFF + b_off + ks * 16 * BPITCH * 2;
                LDX4T(bh + 0, bb);
                LDX4T(bh + 4, bb + 32);
                LDX4T(bl + 0, lb);
                LDX4T(bl + 4, lb + 32);
            }
            const uint32_t abase = sbase + so + AH_OFF + a_off + ks * 32;
            const uint32_t lbase = sbase + so + AL_OFF + a_off + ks * 32;
#pragma unroll
            for (int mi = 0; mi < 4; ++mi) {
                uint32_t ah[4], al[4];
                LDX4(ah, abase + mi * 16 * APITCH * 2);
                LDX4(al, lbase + mi * 16 * APITCH * 2);
#pragma unroll
                for (int ni = 0; ni < 4; ++ni) MMA(acc[mi][ni], ah, bh + ni * 2);
#pragma unroll
                for (int ni = 0; ni < 4; ++ni) MMA(acc[mi][ni], ah, bl + ni * 2);
#pragma unroll
                for (int ni = 0; ni < 4; ++ni) MMA(acc[mi][ni], al, bh + ni * 2);
            }
        }
    }

    // epilogue
#pragma unroll
    for (int mi = 0; mi < 4; ++mi) {
        int row = m0 + wm + mi * 16 + (lane >> 2);
#pragma unroll
        for (int ni = 0; ni < 4; ++ni) {
            int col = n0 + wn + ni * 8 + (lane & 3) * 2;
#pragma unroll
            for (int half = 0; half < 2; ++half) {
                int r = row + half * 8;
                float v0 = acc[mi][ni][half * 2 + 0];
                float v1 = acc[mi][ni][half * 2 + 1];
                size_t idx = (size_t)r * Ncols + col;
                if (EPI == 0) {
                    *(float2*)(C + idx) = make_float2(v0, v1);
                } else {
                    if (EPI == 2) {
                        v0 = gelu1(v0 + bias[col]);
                        v1 = gelu1(v1 + bias[col + 1]);
                    }
                    bf16 h0, l0, h1, l1;
                    split1(v0, h0, l0);
                    split1(v1, h1, l1);
                    __nv_bfloat162 hp = __halves2bfloat162(h0, h1);
                    __nv_bfloat162 lp = __halves2bfloat162(l0, l1);
                    *(uint32_t*)(Ch + idx) = *(uint32_t*)&hp;
                    *(uint32_t*)(Cl + idx) = *(uint32_t*)&lp;
                }
            }
        }
    }
}

// ---------------------------------------------------------------------------
// MMA-based fused attention (R12 version, unchanged).
// ---------------------------------------------------------------------------
#define ATP 72
#define SPITCH 68
#define AQH 0
#define AQL (AQH + 64 * ATP * 2)
#define AKH (AQL + 64 * ATP * 2)
#define AKL (AKH + 64 * ATP * 2)
#define AVH (AKL + 64 * ATP * 2)
#define AVL (AVH + 64 * ATP * 2)
#define APH (AVL + 64 * ATP * 2)
#define APL (APH + 64 * ATP * 2)
#define ASS (APL + 64 * ATP * 2)
#define ASTAT (ASS + 64 * SPITCH * 4)
#define ATT_SMEM (ASTAT + 3 * 64 * 4)

__global__ __launch_bounds__(256, 2)
void attn_kernel(const bf16* __restrict__ qkvh, const bf16* __restrict__ qkvl,
                 const int* __restrict__ mask,
                 bf16* __restrict__ oh, bf16* __restrict__ ol)
{
    extern __shared__ __align__(16) char sm[];
    const uint32_t sb = s2u(sm);
    float* Ss     = (float*)(sm + ASS);
    float* m_s    = (float*)(sm + ASTAT);
    float* l_s    = m_s + 64;
    float* corr_s = l_s + 64;

    const int tid = threadIdx.x, lane = tid & 31, wid = tid >> 5;
    const int bh_i = blockIdx.y, b = bh_i >> 4, h = bh_i & 15;
    const int q0 = blockIdx.x * 64;
    const int wr = (wid & 3) * 16, wc = (wid >> 2) * 32;
    const float scale = 0.125f;
    const size_t rs = 3 * INNER;

    {
        const bf16* qh_g = qkvh + ((size_t)(b * NN + q0)) * rs + h * DHEAD;
        const bf16* ql_g = qkvl + ((size_t)(b * NN + q0)) * rs + h * DHEAD;
        for (int idx = tid; idx < 512; idx += 256) {
            int r = idx >> 3, ch = (idx & 7) * 8;
            size_t off = (size_t)r * rs + ch;
            *(uint4*)(sm + AQH + (r * ATP + ch) * 2) = *(const uint4*)(qh_g + off);
            *(uint4*)(sm + AQL + (r * ATP + ch) * 2) = *(const uint4*)(ql_g + off);
        }
    }
    if (tid < 64) { m_s[tid] = -INFINITY; l_s[tid] = 0.f; }

    float oacc[4][4];
#pragma unroll
    for (int i = 0; i < 4; ++i)
#pragma unroll
        for (int j = 0; j < 4; ++j) oacc[i][j] = 0.f;

    const uint32_t frag_a = ((lane & 15) * ATP + (lane >> 4) * 8) * 2;
    const uint32_t qa  = sb + AQH + wr * ATP * 2 + frag_a;
    const uint32_t qla = sb + AQL + wr * ATP * 2 + frag_a;
    const uint32_t ka  = sb + AKH + wc * ATP * 2 + frag_a;
    const uint32_t kla = sb + AKL + wc * ATP * 2 + frag_a;
    const uint32_t pa  = sb + APH + wr * ATP * 2 + frag_a;
    const uint32_t pla = sb + APL + wr * ATP * 2 + frag_a;
    const uint32_t va  = sb + AVH + ((lane & 15) * ATP + wc + (lane >> 4) * 8) * 2;
    const uint32_t vla = sb + AVL + ((lane & 15) * ATP + wc + (lane >> 4) * 8) * 2;

    for (int kt = 0; kt < NN / 64; ++kt) {
        const int k0 = kt * 64;
        __syncthreads();

        {
            const bf16* kh_g = qkvh + ((size_t)(b * NN + k0)) * rs + INNER + h * DHEAD;
            const bf16* kl_g = qkvl + ((size_t)(b * NN + k0)) * rs + INNER + h * DHEAD;
            for (int idx = tid; idx < 512; idx += 256) {
                int r = idx >> 3, ch = (idx & 7) * 8;
                size_t off = (size_t)r * rs + ch;
                *(uint4*)(sm + AKH + (r * ATP + ch) * 2) = *(const uint4*)(kh_g + off);
                *(uint4*)(sm + AKL + (r * ATP + ch) * 2) = *(const uint4*)(kl_g + off);
                *(uint4*)(sm + AVH + (r * ATP + ch) * 2) = *(const uint4*)(kh_g + INNER + off);
                *(uint4*)(sm + AVL + (r * ATP + ch) * 2) = *(const uint4*)(kl_g + INNER + off);
            }
        }
        __syncthreads();

        float sacc[4][4];
#pragma unroll
        for (int i = 0; i < 4; ++i)
#pragma unroll
            for (int j = 0; j < 4; ++j) sacc[i][j] = 0.f;

#pragma unroll
        for (int kd = 0; kd < 4; ++kd) {
            uint32_t aqh[4], aql[4];
            LDX4(aqh, qa + kd * 32);
            LDX4(aql, qla + kd * 32);
            uint32_t t0[4], t1[4], kh[8], kl[8];
            LDX4(t0, ka + kd * 32);
            LDX4(t1, ka + 16 * ATP * 2 + kd * 32);
            kh[0] = t0[0]; kh[1] = t0[2]; kh[2] = t0[1]; kh[3] = t0[3];
            kh[4] = t1[0]; kh[5] = t1[2]; kh[6] = t1[1]; kh[7] = t1[3];
            LDX4(t0, kla + kd * 32);
            LDX4(t1, kla + 16 * ATP * 2 + kd * 32);
            kl[0] = t0[0]; kl[1] = t0[2]; kl[2] = t0[1]; kl[3] = t0[3];
            kl[4] = t1[0]; kl[5] = t1[2]; kl[6] = t1[1]; kl[7] = t1[3];
#pragma unroll
            for (int nt = 0; nt < 4; ++nt) MMA(sacc[nt], aqh, kh + nt * 2);
#pragma unroll
            for (int nt = 0; nt < 4; ++nt) MMA(sacc[nt], aqh, kl + nt * 2);
#pragma unroll
            for (int nt = 0; nt < 4; ++nt) MMA(sacc[nt], aql, kh + nt * 2);
        }

        {
            const int* mbase = mask + ((size_t)b * NN + q0) * NN + k0;
            int r0 = wr + (lane >> 2), r1 = r0 + 8;
#pragma unroll
            for (int nt = 0; nt < 4; ++nt) {
                int col = wc + nt * 8 + (lane & 3) * 2;
                const int* m0p = mbase + (size_t)r0 * NN + col;
                const int* m1p = mbase + (size_t)r1 * NN + col;
                Ss[r0 * SPITCH + col]     = m0p[0] ? sacc[nt][0] * scale : -1e9f;
                Ss[r0 * SPITCH + col + 1] = m0p[1] ? sacc[nt][1] * scale : -1e9f;
                Ss[r1 * SPITCH + col]     = m1p[0] ? sacc[nt][2] * scale : -1e9f;
                Ss[r1 * SPITCH + col + 1] = m1p[1] ? sacc[nt][3] * scale : -1e9f;
            }
        }
        __syncthreads();

        {
            int r = tid >> 2, q = tid & 3;
            float* row = &Ss[r * SPITCH + q * 16];
            float mx = m_s[r];
            float tmax = -INFINITY;
#pragma unroll
            for (int j = 0; j < 16; ++j) tmax = fmaxf(tmax, row[j]);
            tmax = fmaxf(tmax, __shfl_xor_sync(~0u, tmax, 1));
            tmax = fmaxf(tmax, __shfl_xor_sync(~0u, tmax, 2));
            float nm = fmaxf(mx, tmax);
            float sum = 0.f;
#pragma unroll
            for (int j = 0; j < 16; ++j) {
                float p = __expf(row[j] - nm);
                row[j] = p;
                sum += p;
            }
            sum += __shfl_xor_sync(~0u, sum, 1);
            sum += __shfl_xor_sync(~0u, sum, 2);
            if (q == 0) {
                float corr = __expf(mx - nm);
                m_s[r] = nm;
                l_s[r] = l_s[r] * corr + sum;
                corr_s[r] = corr;
            }
        }
        __syncthreads();

        for (int idx = tid; idx < 512; idx += 256) {
            int r = idx >> 3, ch = (idx & 7) * 8;
            float4 p0 = *(float4*)&Ss[r * SPITCH + ch];
            float4 p1 = *(float4*)&Ss[r * SPITCH + ch + 4];
            bf16 h0, l0, h1, l1, h2, l2, h3, l3, h4, l4, h5, l5, h6, l6, h7, l7;
            split1(p0.x, h0, l0); split1(p0.y, h1, l1);
            split1(p0.z, h2, l2); split1(p0.w, h3, l3);
            split1(p1.x, h4, l4); split1(p1.y, h5, l5);
            split1(p1.z, h6, l6); split1(p1.w, h7, l7);
            __nv_bfloat162 a0 = __halves2bfloat162(h0, h1), a1 = __halves2bfloat162(h2, h3);
            __nv_bfloat162 a2 = __halves2bfloat162(h4, h5), a3 = __halves2bfloat162(h6, h7);
            __nv_bfloat162 c0 = __halves2bfloat162(l0, l1), c1 = __halves2bfloat162(l2, l3);
            __nv_bfloat162 c2 = __halves2bfloat162(l4, l5), c3 = __halves2bfloat162(l6, l7);
            *(uint4*)(sm + APH + (r * ATP + ch) * 2) =
                make_uint4(*(uint32_t*)&a0, *(uint32_t*)&a1, *(uint32_t*)&a2, *(uint32_t*)&a3);
            *(uint4*)(sm + APL + (r * ATP + ch) * 2) =
                make_uint4(*(uint32_t*)&c0, *(uint32_t*)&c1, *(uint32_t*)&c2, *(uint32_t*)&c3);
        }
        __syncthreads();

        {
            float c0 = corr_s[wr + (lane >> 2)];
            float c1 = corr_s[wr + (lane >> 2) + 8];
#pragma unroll
            for (int nt = 0; nt < 4; ++nt) {
                oacc[nt][0] *= c0; oacc[nt][1] *= c0;
                oacc[nt][2] *= c1; oacc[nt][3] *= c1;
            }
        }
#pragma unroll
        for (int kd = 0; kd < 4; ++kd) {
            uint32_t ap[4], apl[4];
            LDX4(ap,  pa  + kd * 32);
            LDX4(apl, pla + kd * 32);
            uint32_t vh[8], vl[8];
            LDX4T(vh + 0, va  + kd * (16 * ATP * 2));
            LDX4T(vh + 4, va  + kd * (16 * ATP * 2) + 32);
            LDX4T(vl + 0, vla + kd * (16 * ATP * 2));
            LDX4T(vl + 4, vla + kd * (16 * ATP * 2) + 32);
#pragma unroll
            for (int nt = 0; nt < 4; ++nt) MMA(oacc[nt], ap,  vh + nt * 2);
#pragma unroll
            for (int nt = 0; nt < 4; ++nt) MMA(oacc[nt], ap,  vl + nt * 2);
#pragma unroll
            for (int nt = 0; nt < 4; ++nt) MMA(oacc[nt], apl, vh + nt * 2);
        }
    }

    {
        int r0 = wr + (lane >> 2), r1 = r0 + 8;
        float il0 = 1.f / l_s[r0];
        float il1 = 1.f / l_s[r1];
        size_t base0 = ((size_t)(b * NN + q0 + r0)) * INNER + h * DHEAD;
        size_t base1 = ((size_t)(b * NN + q0 + r1)) * INNER + h * DHEAD;
#pragma unroll
        for (int nt = 0; nt < 4; ++nt) {
            int col = wc + nt * 8 + (lane & 3) * 2;
            float v0 = oacc[nt][0] * il0, v1 = oacc[nt][1] * il0;
            float v2 = oacc[nt][2] * il1, v3 = oacc[nt][3] * il1;
            bf16 h0, l0, h1, l1;
            split1(v0, h0, l0); split1(v1, h1, l1);
            __nv_bfloat162 hp = __halves2bfloat162(h0, h1);
            __nv_bfloat162 lp = __halves2bfloat162(l0, l1);
            *(uint32_t*)(oh + base0 + col) = *(uint32_t*)&hp;
            *(uint32_t*)(ol + base0 + col) = *(uint32_t*)&lp;
            split1(v2, h0, l0); split1(v3, h1, l1);
            hp = __halves2bfloat162(h0, h1);
            lp = __halves2bfloat162(l0, l1);
            *(uint32_t*)(oh + base1 + col) = *(uint32_t*)&hp;
            *(uint32_t*)(ol + base1 + col) = *(uint32_t*)&lp;
        }
    }
}

// ---------------------------------------------------------------------------
// Launch
// ---------------------------------------------------------------------------
extern "C" void kernel_launch(void* const* d_in, const int* in_sizes, int n_in,
                              void* d_out, int out_size)
{
    const float* x_in  = (const float*)d_in[0];
    const int*   mask  = (const int*)  d_in[1];
    const float* ln1_g = (const float*)d_in[2];
    const float* ln1_b = (const float*)d_in[3];
    const float* qkv_w = (const float*)d_in[4];
    const float* out_w = (const float*)d_in[5];
    const float* out_b = (const float*)d_in[6];
    const float* ln2_g = (const float*)d_in[7];
    const float* ln2_b = (const float*)d_in[8];
    const float* ff1_w = (const float*)d_in[9];
    const float* ff1_b = (const float*)d_in[10];
    const float* ff2_w = (const float*)d_in[11];
    const float* ff2_b = (const float*)d_in[12];
    float* x = (float*)d_out;

    float* part;
    bf16 *qkvh, *qkvl, *hh, *hl, *h2h, *h2l, *oh, *ol;
    bf16 *wqh, *wql, *woh, *wol, *wf1h, *wf1l, *wf2h, *wf2l;
    cudaGetSymbolAddress((void**)&part, g_part);
    cudaGetSymbolAddress((void**)&qkvh, g_qkvh); cudaGetSymbolAddress((void**)&qkvl, g_qkvl);
    cudaGetSymbolAddress((void**)&hh,  g_hh);  cudaGetSymbolAddress((void**)&hl,  g_hl);
    cudaGetSymbolAddress((void**)&h2h, g_h2h); cudaGetSymbolAddress((void**)&h2l, g_h2l);
    cudaGetSymbolAddress((void**)&oh,  g_oh);  cudaGetSymbolAddress((void**)&ol,  g_ol);
    cudaGetSymbolAddress((void**)&wqh, g_wqkv_h); cudaGetSymbolAddress((void**)&wql, g_wqkv_l);
    cudaGetSymbolAddress((void**)&woh, g_wout_h); cudaGetSymbolAddress((void**)&wol, g_wout_l);
    cudaGetSymbolAddress((void**)&wf1h, g_wff1_h); cudaGetSymbolAddress((void**)&wf1l, g_wff1_l);
    cudaGetSymbolAddress((void**)&wf2h, g_wff2_h); cudaGetSymbolAddress((void**)&wf2l, g_wff2_l);

    cudaFuncSetAttribute(attn_kernel,
                         cudaFuncAttributeMaxDynamicSharedMemorySize, ATT_SMEM);
    cudaFuncSetAttribute(mma_gemm<0>,
                         cudaFuncAttributeMaxDynamicSharedMemorySize, GEMM_SMEM);
    cudaFuncSetAttribute(mma_gemm<2>,
                         cudaFuncAttributeMaxDynamicSharedMemorySize, GEMM_SMEM);
    cudaFuncSetAttribute(mma_gemm<3>,
                         cudaFuncAttributeMaxDynamicSharedMemorySize, GEMM_SMEM);

    cvt_kernel<<<4096, 256>>>(qkv_w, wqh, wql, DEPTH * DIMM * 3 * INNER / 4);
    cvt_kernel<<<2048, 256>>>(out_w, woh, wol, DEPTH * INNER * DIMM / 4);
    cvt_kernel<<<4096, 256>>>(ff1_w, wf1h, wf1l, DEPTH * DIMM * MLPD / 4);
    cvt_kernel<<<4096, 256>>>(ff2_w, wf2h, wf2l, DEPTH * MLPD * DIMM / 4);

    cudaMemcpyAsync(x, x_in, sizeof(float) * (size_t)TOK * DIMM,
                    cudaMemcpyDeviceToDevice);

    const int RED_N4 = TOK * DIMM / 4;

    for (int l = 0; l < DEPTH; ++l) {
        size_t wq = (size_t)l * DIMM * 3 * INNER;
        size_t wo = (size_t)l * INNER * DIMM;
        size_t w1 = (size_t)l * DIMM * MLPD;
        size_t w2 = (size_t)l * MLPD * DIMM;

        // ln1: layer 0 plain; layers 1..3 fused with previous ff2 reduce
        if (l == 0) {
            red_ln_kernel<0><<<TOK, 256>>>(x, nullptr, nullptr,
                                           ln1_g, ln1_b, hh, hl);
        } else {
            red_ln_kernel<4><<<TOK, 256>>>(x, ff2_b + (size_t)(l - 1) * DIMM,
                                           part,
                                           ln1_g + (size_t)l * DIMM,
                                           ln1_b + (size_t)l * DIMM, hh, hl);
        }
        // qkv -> bf16 hi/lo directly
        mma_gemm<3><<<dim3(3 * INNER / 128, TOK / 128, 1), 256, GEMM_SMEM>>>(
            hh, hl, wqh + wq, wql + wq, nullptr, nullptr, qkvh, qkvl,
            TOK, 3 * INNER, DIMM, DIMM);
        attn_kernel<<<dim3(NN / 64, BB * HEADS), 256, ATT_SMEM>>>(
            qkvh, qkvl, mask, oh, ol);
        // out-proj: split-K 2 -> partials
        mma_gemm<0><<<dim3(DIMM / 128, TOK / 128, 2), 256, GEMM_SMEM>>>(
            oh, ol, woh + wo, wol + wo, part, nullptr, nullptr, nullptr,
            TOK, DIMM, INNER, INNER / 2);
        // fused: x += out_b + parts ; ln2(x) -> hh, hl
        red_ln_kernel<2><<<TOK, 256>>>(x, out_b + (size_t)l * DIMM, part,
                                       ln2_g + (size_t)l * DIMM,
                                       ln2_b + (size_t)l * DIMM, hh, hl);
        // ff1 + GELU -> bf16 hi/lo
        mma_gemm<2><<<dim3(MLPD / 128, TOK / 128, 1), 256, GEMM_SMEM>>>(
            hh, hl, wf1h + w1, wf1l + w1, nullptr, ff1_b + (size_t)l * MLPD,
            h2h, h2l, TOK, MLPD, DIMM, DIMM);
        // ff2: split-K 4 -> partials (reduce deferred to next ln1 or final)
        mma_gemm<0><<<dim3(DIMM / 128, TOK / 128, 4), 256, GEMM_SMEM>>>(
            h2h, h2l, wf2h + w2, wf2l + w2, part, nullptr, nullptr, nullptr,
            TOK, DIMM, MLPD, MLPD / 4);
    }
    // final residual update (no LN after last layer)
    reduce_kernel<4><<<RED_N4 / 256, 256>>>(x, ff2_b + (size_t)(DEPTH - 1) * DIMM,
                                            part, RED_N4);
}

// round 16
// speedup vs baseline: 1.1862x; 1.0707x over previous
#include <cuda_runtime.h>
#include <cuda_bf16.h>
#include <math.h>
#include <stdint.h>

// Problem constants
#define BB     2
#define NN     1024
#define DIMM   1024
#define DEPTH  4
#define HEADS  16
#define DHEAD  64
#define INNER  1024
#define MLPD   4096
#define TOK    (BB*NN)       // 2048

typedef __nv_bfloat16 bf16;

// ---------------------------------------------------------------------------
// Scratch (no cudaMalloc allowed)
// ---------------------------------------------------------------------------
__device__ float g_part[4 * TOK * DIMM];

__device__ bf16 g_qkvh[TOK * 3 * INNER], g_qkvl[TOK * 3 * INNER];
__device__ bf16 g_hh [TOK * DIMM],  g_hl [TOK * DIMM];
__device__ bf16 g_h2h[TOK * MLPD],  g_h2l[TOK * MLPD];
__device__ bf16 g_oh [TOK * INNER], g_ol [TOK * INNER];

__device__ bf16 g_wqkv_h[DEPTH * DIMM * 3 * INNER], g_wqkv_l[DEPTH * DIMM * 3 * INNER];
__device__ bf16 g_wout_h[DEPTH * INNER * DIMM],     g_wout_l[DEPTH * INNER * DIMM];
__device__ bf16 g_wff1_h[DEPTH * DIMM * MLPD],      g_wff1_l[DEPTH * DIMM * MLPD];
__device__ bf16 g_wff2_h[DEPTH * MLPD * DIMM],      g_wff2_l[DEPTH * MLPD * DIMM];

// ---------------------------------------------------------------------------
// Helpers
// ---------------------------------------------------------------------------
__device__ __forceinline__ uint32_t s2u(const void* p) {
    uint32_t a;
    asm("{ .reg .u64 t; cvta.to.shared.u64 t, %1; cvt.u32.u64 %0, t; }"
        : "=r"(a) : "l"(p));
    return a;
}

__device__ __forceinline__ void split1(float x, bf16& h, bf16& l) {
    h = __float2bfloat16(x);
    l = __float2bfloat16(x - __bfloat162float(h));
}

__device__ __forceinline__ void splitpair(float x0, float x1,
                                          uint32_t& h, uint32_t& l) {
    bf16 h0, l0, h1, l1;
    split1(x0, h0, l0);
    split1(x1, h1, l1);
    __nv_bfloat162 hp = __halves2bfloat162(h0, h1);
    __nv_bfloat162 lp = __halves2bfloat162(l0, l1);
    h = *reinterpret_cast<uint32_t*>(&hp);
    l = *reinterpret_cast<uint32_t*>(&lp);
}

#define LDX4(r, addr) \
    asm volatile("ldmatrix.sync.aligned.m8n8.x4.shared.b16 {%0,%1,%2,%3}, [%4];" \
        : "=r"((r)[0]), "=r"((r)[1]), "=r"((r)[2]), "=r"((r)[3]) : "r"(addr))

#define LDX4T(r, addr) \
    asm volatile("ldmatrix.sync.aligned.m8n8.x4.trans.shared.b16 {%0,%1,%2,%3}, [%4];" \
        : "=r"((r)[0]), "=r"((r)[1]), "=r"((r)[2]), "=r"((r)[3]) : "r"(addr))

#define MMA(cd, a, b) \
    asm volatile("mma.sync.aligned.m16n8k16.row.col.f32.bf16.bf16.f32 " \
        "{%0,%1,%2,%3}, {%4,%5,%6,%7}, {%8,%9}, {%0,%1,%2,%3};" \
        : "+f"((cd)[0]), "+f"((cd)[1]), "+f"((cd)[2]), "+f"((cd)[3]) \
        : "r"((a)[0]), "r"((a)[1]), "r"((a)[2]), "r"((a)[3]), \
          "r"((b)[0]), "r"((b)[1]))

#define CP16(dst, src) \
    asm volatile("cp.async.cg.shared.global [%0], [%1], 16;" \
        :: "r"(dst), "l"(src) : "memory")

__device__ __forceinline__ float gelu1(float v) {
    return 0.5f * v * (1.f + erff(v * 0.70710678118654752f));
}

// ---------------------------------------------------------------------------
// fp32 -> bf16 hi/lo elementwise convert
// ---------------------------------------------------------------------------
__global__ void cvt_kernel(const float* __restrict__ in,
                           bf16* __restrict__ h, bf16* __restrict__ l, int n4)
{
    for (int i = blockIdx.x * blockDim.x + threadIdx.x; i < n4;
         i += gridDim.x * blockDim.x) {
        float4 v = ((const float4*)in)[i];
        uint32_t h0, l0, h1, l1;
        splitpair(v.x, v.y, h0, l0);
        splitpair(v.z, v.w, h1, l1);
        ((uint2*)h)[i] = make_uint2(h0, h1);
        ((uint2*)l)[i] = make_uint2(l0, l1);
    }
}

// ---------------------------------------------------------------------------
// Split-K reduce (standalone, used after the last layer's ff2)
// ---------------------------------------------------------------------------
template <int NP>
__global__ void reduce_kernel(float* __restrict__ x,
                              const float* __restrict__ bias,
                              const float* __restrict__ part, int n4)
{
    int i = blockIdx.x * blockDim.x + threadIdx.x;
    if (i >= n4) return;
    float4 v = ((const float4*)x)[i];
    float4 b = ((const float4*)bias)[i & (DIMM / 4 - 1)];
    v.x += b.x; v.y += b.y; v.z += b.z; v.w += b.w;
#pragma unroll
    for (int p = 0; p < NP; ++p) {
        float4 pv = ((const float4*)(part + (size_t)p * TOK * DIMM))[i];
        v.x += pv.x; v.y += pv.y; v.z += pv.z; v.w += pv.w;
    }
    ((float4*)x)[i] = v;
}

// ---------------------------------------------------------------------------
// Fused split-K reduce + residual update + LayerNorm -> bf16 hi/lo.
// ---------------------------------------------------------------------------
template <int NP>
__global__ void red_ln_kernel(float* __restrict__ x,
                              const float* __restrict__ bias,
                              const float* __restrict__ part,
                              const float* __restrict__ g,
                              const float* __restrict__ b,
                              bf16* __restrict__ oh, bf16* __restrict__ ol)
{
    int row = blockIdx.x;
    int tid = threadIdx.x;
    int lane = tid & 31, wid = tid >> 5;
    __shared__ float red[8];
    __shared__ float bc[2];

    size_t i4 = (size_t)row * (DIMM / 4) + tid;
    float4 v = ((const float4*)x)[i4];

    if (NP > 0) {
        float4 bb = ((const float4*)bias)[tid];
        v.x += bb.x; v.y += bb.y; v.z += bb.z; v.w += bb.w;
#pragma unroll
        for (int p = 0; p < NP; ++p) {
            float4 pv = ((const float4*)(part + (size_t)p * TOK * DIMM))[i4];
            v.x += pv.x; v.y += pv.y; v.z += pv.z; v.w += pv.w;
        }
        ((float4*)x)[i4] = v;
    }

    float s = v.x + v.y + v.z + v.w;
#pragma unroll
    for (int o = 16; o > 0; o >>= 1) s += __shfl_xor_sync(~0u, s, o);
    if (lane == 0) red[wid] = s;
    __syncthreads();
    if (tid == 0) {
        float t = 0.f;
#pragma unroll
        for (int i = 0; i < 8; ++i) t += red[i];
        bc[0] = t * (1.f / DIMM);
    }
    __syncthreads();
    float mu = bc[0];

    float dx = v.x - mu, dy = v.y - mu, dz = v.z - mu, dw = v.w - mu;
    float s2 = dx * dx + dy * dy + dz * dz + dw * dw;
#pragma unroll
    for (int o = 16; o > 0; o >>= 1) s2 += __shfl_xor_sync(~0u, s2, o);
    if (lane == 0) red[wid] = s2;
    __syncthreads();
    if (tid == 0) {
        float t = 0.f;
#pragma unroll
        for (int i = 0; i < 8; ++i) t += red[i];
        bc[1] = rsqrtf(t * (1.f / DIMM) + 1e-5f);
    }
    __syncthreads();
    float rstd = bc[1];

    float4 gg = *(const float4*)(g + tid * 4);
    float4 bb2 = *(const float4*)(b + tid * 4);
    float o0 = dx * rstd * gg.x + bb2.x;
    float o1 = dy * rstd * gg.y + bb2.y;
    float o2 = dz * rstd * gg.z + bb2.z;
    float o3 = dw * rstd * gg.w + bb2.w;

    uint32_t h0, l0, h1, l1;
    splitpair(o0, o1, h0, l0);
    splitpair(o2, o3, h1, l1);
    size_t idx = (size_t)row * DIMM + tid * 4;
    *(uint2*)(oh + idx) = make_uint2(h0, h1);
    *(uint2*)(ol + idx) = make_uint2(l0, l1);
}

// ---------------------------------------------------------------------------
// Tensor-core GEMM (R12 config): bf16 hi/lo, 3-term split MMA, fp32 accum.
// 128x128 tile/CTA, 256 threads (8 warps x 64x32), K-chunk 32, 2-stage ring.
// EPI: 0 plain fp32, 2 +bias+GELU -> bf16 h/l, 3 plain -> bf16 h/l
// ---------------------------------------------------------------------------
#define APITCH 40
#define BPITCH 136
#define AH_OFF 0
#define AL_OFF (128 * APITCH * 2)
#define BH_OFF (2 * 128 * APITCH * 2)
#define BL_OFF (BH_OFF + 32 * BPITCH * 2)
#define STG_TOTAL (BL_OFF + 32 * BPITCH * 2)     // 37888
#define GEMM_SMEM (2 * STG_TOTAL)                // 75776

template <int EPI>
__global__ __launch_bounds__(256, 2)
void mma_gemm(const bf16* __restrict__ Ah, const bf16* __restrict__ Al,
              const bf16* __restrict__ Bh, const bf16* __restrict__ Bl,
              float* __restrict__ C, const float* __restrict__ bias,
              bf16* __restrict__ Ch, bf16* __restrict__ Cl,
              int M, int Ncols, int lda, int Kpart)
{
    extern __shared__ __align__(16) char smem[];
    const uint32_t sbase = s2u(smem);

    const int tid = threadIdx.x, lane = tid & 31, wid = tid >> 5;
    const int m0 = blockIdx.y * 128, n0 = blockIdx.x * 128;
    const int wm = (wid >> 2) * 64, wn = (wid & 3) * 32;
    const int koff = blockIdx.z * Kpart;
    C += (size_t)blockIdx.z * M * Ncols;

    float acc[4][4][4];
#pragma unroll
    for (int i = 0; i < 4; ++i)
#pragma unroll
        for (int j = 0; j < 4; ++j)
#pragma unroll
            for (int q = 0; q < 4; ++q) acc[i][j][q] = 0.f;

    const uint32_t a_off = ((wm + (lane & 15)) * APITCH + (lane >> 4) * 8) * 2;
    const uint32_t b_off = ((lane & 15) * BPITCH + wn + (lane >> 4) * 8) * 2;

    const int NCH = Kpart / 32;

    auto issue = [&](int cc, uint32_t so) {
#pragma unroll
        for (int i = 0; i < 2; ++i) {
            int idx = tid + i * 256;
            int arow = idx >> 2, akc = (idx & 3) * 8;
            CP16(sbase + so + AH_OFF + (arow * APITCH + akc) * 2,
                 Ah + (size_t)(m0 + arow) * lda + koff + cc * 32 + akc);
            CP16(sbase + so + AL_OFF + (arow * APITCH + akc) * 2,
                 Al + (size_t)(m0 + arow) * lda + koff + cc * 32 + akc);
            int bkr = idx >> 4, bn = (idx & 15) * 8;
            CP16(sbase + so + BH_OFF + (bkr * BPITCH + bn) * 2,
                 Bh + (size_t)(koff + cc * 32 + bkr) * Ncols + n0 + bn);
            CP16(sbase + so + BL_OFF + (bkr * BPITCH + bn) * 2,
                 Bl + (size_t)(koff + cc * 32 + bkr) * Ncols + n0 + bn);
        }
        asm volatile("cp.async.commit_group;" ::: "memory");
    };

    issue(0, 0);

    for (int c = 0; c < NCH; ++c) {
        const uint32_t so = (uint32_t)(c & 1) * STG_TOTAL;
        __syncthreads();
        if (c + 1 < NCH) {
            issue(c + 1, (uint32_t)((c + 1) & 1) * STG_TOTAL);
            asm volatile("cp.async.wait_group 1;" ::: "memory");
        } else {
            asm volatile("cp.async.wait_group 0;" ::: "memory");
        }
        __syncthreads();

#pragma unroll
        for (int ks = 0; ks < 2; ++ks) {
            uint32_t bh[8], bl[8];
            {
                uint32_t bb = sbase + so + BH_OFF + b_off + ks * 16 * BPITCH * 2;
                uint32_t lb = sbase + so + BL_OFF + b_off + ks * 16 * BPITCH * 2;
                LDX4T(bh + 0, bb);
                LDX4T(bh + 4, bb + 32);
                LDX4T(bl + 0, lb);
                LDX4T(bl + 4, lb + 32);
            }
            const uint32_t abase = sbase + so + AH_OFF + a_off + ks * 32;
            const uint32_t lbase = sbase + so + AL_OFF + a_off + ks * 32;
#pragma unroll
            for (int mi = 0; mi < 4; ++mi) {
                uint32_t ah[4], al[4];
                LDX4(ah, abase + mi * 16 * APITCH * 2);
                LDX4(al, lbase + mi * 16 * APITCH * 2);
#pragma unroll
                for (int ni = 0; ni < 4; ++ni) MMA(acc[mi][ni], ah, bh + ni * 2);
#pragma unroll
                for (int ni = 0; ni < 4; ++ni) MMA(acc[mi][ni], ah, bl + ni * 2);
#pragma unroll
                for (int ni = 0; ni < 4; ++ni) MMA(acc[mi][ni], al, bh + ni * 2);
            }
        }
    }

#pragma unroll
    for (int mi = 0; mi < 4; ++mi) {
        int row = m0 + wm + mi * 16 + (lane >> 2);
#pragma unroll
        for (int ni = 0; ni < 4; ++ni) {
            int col = n0 + wn + ni * 8 + (lane & 3) * 2;
#pragma unroll
            for (int half = 0; half < 2; ++half) {
                int r = row + half * 8;
                float v0 = acc[mi][ni][half * 2 + 0];
                float v1 = acc[mi][ni][half * 2 + 1];
                size_t idx = (size_t)r * Ncols + col;
                if (EPI == 0) {
                    *(float2*)(C + idx) = make_float2(v0, v1);
                } else {
                    if (EPI == 2) {
                        v0 = gelu1(v0 + bias[col]);
                        v1 = gelu1(v1 + bias[col + 1]);
                    }
                    uint32_t hp, lp;
                    splitpair(v0, v1, hp, lp);
                    *(uint32_t*)(Ch + idx) = hp;
                    *(uint32_t*)(Cl + idx) = lp;
                }
            }
        }
    }
}

// ---------------------------------------------------------------------------
// Flash-attention v2 style MMA attention, fully register-resident softmax.
// CTA: 128 threads (4 warps), 64 q-rows of one (b,h). Each warp owns 16 full
// rows (all 64 k-cols). P converts from C-fragments directly to A-fragments.
// ---------------------------------------------------------------------------
#define A2P 72
#define QH2 0
#define QL2 (QH2 + 64 * A2P * 2)     // 9216
#define KH2 (QL2 + 64 * A2P * 2)
#define KL2 (KH2 + 64 * A2P * 2)
#define VH2 (KL2 + 64 * A2P * 2)
#define VL2 (VH2 + 64 * A2P * 2)
#define ATT_SMEM (VL2 + 64 * A2P * 2)   // 55296

__global__ __launch_bounds__(128, 3)
void attn_kernel(const bf16* __restrict__ qkvh, const bf16* __restrict__ qkvl,
                 const int* __restrict__ mask,
                 bf16* __restrict__ oh, bf16* __restrict__ ol)
{
    extern __shared__ __align__(16) char sm[];
    const uint32_t sb = s2u(sm);

    const int tid = threadIdx.x, lane = tid & 31, wid = tid >> 5;
    const int bh_i = blockIdx.y, b = bh_i >> 4, h = bh_i & 15;
    const int q0 = blockIdx.x * 64;
    const int wr = wid * 16;
    const int grp = lane >> 2, tc = lane & 3;
    const float scale = 0.125f;
    const size_t rs = 3 * INNER;

    // load Q tile (64x64) hi/lo into smem
    {
        const bf16* qh_g = qkvh + ((size_t)(b * NN + q0)) * rs + h * DHEAD;
        const bf16* ql_g = qkvl + ((size_t)(b * NN + q0)) * rs + h * DHEAD;
        for (int idx = tid; idx < 512; idx += 128) {
            int r = idx >> 3, ch = (idx & 7) * 8;
            size_t off = (size_t)r * rs + ch;
            *(uint4*)(sm + QH2 + (r * A2P + ch) * 2) = *(const uint4*)(qh_g + off);
            *(uint4*)(sm + QL2 + (r * A2P + ch) * 2) = *(const uint4*)(ql_g + off);
        }
    }
    __syncthreads();

    // per-lane fragment address pattern (shared by Q, K, V bases)
    const uint32_t frag_a = ((lane & 15) * A2P + (lane >> 4) * 8) * 2;

    // Q fragments resident in registers for the whole kernel
    uint32_t qh[4][4], ql[4][4];
    {
        uint32_t qa  = sb + QH2 + wr * A2P * 2 + frag_a;
        uint32_t qla = sb + QL2 + wr * A2P * 2 + frag_a;
#pragma unroll
        for (int kd = 0; kd < 4; ++kd) {
            LDX4(qh[kd], qa + kd * 32);
            LDX4(ql[kd], qla + kd * 32);
        }
    }

    const uint32_t ka  = sb + KH2 + frag_a;
    const uint32_t kla = sb + KL2 + frag_a;
    const uint32_t va  = sb + VH2 + frag_a;
    const uint32_t vla = sb + VL2 + frag_a;

    float m0 = -INFINITY, m1 = -INFINITY, l0 = 0.f, l1 = 0.f;
    float oacc[8][4];
#pragma unroll
    for (int i = 0; i < 8; ++i)
#pragma unroll
        for (int j = 0; j < 4; ++j) oacc[i][j] = 0.f;

    for (int kt = 0; kt < NN / 64; ++kt) {
        const int k0 = kt * 64;
        __syncthreads();   // K/V reads from prev iter done before overwrite

        // load K,V tiles hi/lo
        {
            const bf16* kh_g = qkvh + ((size_t)(b * NN + k0)) * rs + INNER + h * DHEAD;
            const bf16* kl_g = qkvl + ((size_t)(b * NN + k0)) * rs + INNER + h * DHEAD;
            for (int idx = tid; idx < 512; idx += 128) {
                int r = idx >> 3, ch = (idx & 7) * 8;
                size_t off = (size_t)r * rs + ch;
                *(uint4*)(sm + KH2 + (r * A2P + ch) * 2) = *(const uint4*)(kh_g + off);
                *(uint4*)(sm + KL2 + (r * A2P + ch) * 2) = *(const uint4*)(kl_g + off);
                *(uint4*)(sm + VH2 + (r * A2P + ch) * 2) = *(const uint4*)(kh_g + INNER + off);
                *(uint4*)(sm + VL2 + (r * A2P + ch) * 2) = *(const uint4*)(kl_g + INNER + off);
            }
        }
        __syncthreads();

        // ---- S = Q K^T (16 rows x 64 cols per warp, 3-term split) ----
        float sacc[8][4];
#pragma unroll
        for (int i = 0; i < 8; ++i)
#pragma unroll
            for (int j = 0; j < 4; ++j) sacc[i][j] = 0.f;

#pragma unroll
        for (int kd = 0; kd < 4; ++kd) {
            uint32_t bh[16], bl[16];
#pragma unroll
            for (int sblk = 0; sblk < 4; ++sblk) {
                uint32_t t[4];
                LDX4(t, ka + sblk * 16 * A2P * 2 + kd * 32);
                bh[4 * sblk + 0] = t[0]; bh[4 * sblk + 1] = t[2];
                bh[4 * sblk + 2] = t[1]; bh[4 * sblk + 3] = t[3];
                LDX4(t, kla + sblk * 16 * A2P * 2 + kd * 32);
                bl[4 * sblk + 0] = t[0]; bl[4 * sblk + 1] = t[2];
                bl[4 * sblk + 2] = t[1]; bl[4 * sblk + 3] = t[3];
            }
#pragma unroll
            for (int nt = 0; nt < 8; ++nt) MMA(sacc[nt], qh[kd], bh + nt * 2);
#pragma unroll
            for (int nt = 0; nt < 8; ++nt) MMA(sacc[nt], qh[kd], bl + nt * 2);
#pragma unroll
            for (int nt = 0; nt < 8; ++nt) MMA(sacc[nt], ql[kd], bh + nt * 2);
        }

        // ---- mask + scale (direct from gmem) ----
        {
            int row0 = q0 + wr + grp;
            const int* mrow0 = mask + ((size_t)b * NN + row0) * NN + k0 + tc * 2;
            const int* mrow1 = mrow0 + (size_t)8 * NN;
#pragma unroll
            for (int nt = 0; nt < 8; ++nt) {
                int2 mv0 = *(const int2*)(mrow0 + nt * 8);
                int2 mv1 = *(const int2*)(mrow1 + nt * 8);
                sacc[nt][0] = mv0.x ? sacc[nt][0] * scale : -1e9f;
                sacc[nt][1] = mv0.y ? sacc[nt][1] * scale : -1e9f;
                sacc[nt][2] = mv1.x ? sacc[nt][2] * scale : -1e9f;
                sacc[nt][3] = mv1.y ? sacc[nt][3] * scale : -1e9f;
            }
        }

        // ---- register-resident online softmax (rows live in lane quads) ----
        {
            float t0 = -INFINITY, t1 = -INFINITY;
#pragma unroll
            for (int nt = 0; nt < 8; ++nt) {
                t0 = fmaxf(t0, fmaxf(sacc[nt][0], sacc[nt][1]));
                t1 = fmaxf(t1, fmaxf(sacc[nt][2], sacc[nt][3]));
            }
            t0 = fmaxf(t0, __shfl_xor_sync(~0u, t0, 1));
            t0 = fmaxf(t0, __shfl_xor_sync(~0u, t0, 2));
            t1 = fmaxf(t1, __shfl_xor_sync(~0u, t1, 1));
            t1 = fmaxf(t1, __shfl_xor_sync(~0u, t1, 2));
            float nm0 = fmaxf(m0, t0), nm1 = fmaxf(m1, t1);
            float c0 = __expf(m0 - nm0), c1 = __expf(m1 - nm1);
            m0 = nm0; m1 = nm1;
            float s0 = 0.f, s1 = 0.f;
#pragma unroll
            for (int nt = 0; nt < 8; ++nt) {
                sacc[nt][0] = __expf(sacc[nt][0] - nm0);
                sacc[nt][1] = __expf(sacc[nt][1] - nm0);
                sacc[nt][2] = __expf(sacc[nt][2] - nm1);
                sacc[nt][3] = __expf(sacc[nt][3] - nm1);
                s0 += sacc[nt][0] + sacc[nt][1];
                s1 += sacc[nt][2] + sacc[nt][3];
            }
            s0 += __shfl_xor_sync(~0u, s0, 1);
            s0 += __shfl_xor_sync(~0u, s0, 2);
            s1 += __shfl_xor_sync(~0u, s1, 1);
            s1 += __shfl_xor_sync(~0u, s1, 2);
            l0 = l0 * c0 + s0;
            l1 = l1 * c1 + s1;
#pragma unroll
            for (int nt = 0; nt < 8; ++nt) {
                oacc[nt][0] *= c0; oacc[nt][1] *= c0;
                oacc[nt][2] *= c1; oacc[nt][3] *= c1;
            }
        }

        // ---- O += P V : P A-fragments built directly from sacc registers ----
#pragma unroll
        for (int kd = 0; kd < 4; ++kd) {
            uint32_t ph[4], pl[4];
            splitpair(sacc[2 * kd][0],     sacc[2 * kd][1],     ph[0], pl[0]);
            splitpair(sacc[2 * kd][2],     sacc[2 * kd][3],     ph[1], pl[1]);
            splitpair(sacc[2 * kd + 1][0], sacc[2 * kd + 1][1], ph[2], pl[2]);
            splitpair(sacc[2 * kd + 1][2], sacc[2 * kd + 1][3], ph[3], pl[3]);

            uint32_t vh[16], vl[16];
#pragma unroll
            for (int j = 0; j < 4; ++j) {
                LDX4T(vh + 4 * j, va  + kd * (16 * A2P * 2) + j * 32);
                LDX4T(vl + 4 * j, vla + kd * (16 * A2P * 2) + j * 32);
            }
#pragma unroll
            for (int nt = 0; nt < 8; ++nt) MMA(oacc[nt], ph, vh + nt * 2);
#pragma unroll
            for (int nt = 0; nt < 8; ++nt) MMA(oacc[nt], ph, vl + nt * 2);
#pragma unroll
            for (int nt = 0; nt < 8; ++nt) MMA(oacc[nt], pl, vh + nt * 2);
        }
    }

    // ---- write O (normalized) as bf16 hi/lo ----
    {
        float il0 = 1.f / l0, il1 = 1.f / l1;
        int r0 = q0 + wr + grp, r1 = r0 + 8;
        size_t base0 = ((size_t)(b * NN + r0)) * INNER + h * DHEAD;
        size_t base1 = ((size_t)(b * NN + r1)) * INNER + h * DHEAD;
#pragma unroll
        for (int nt = 0; nt < 8; ++nt) {
            int col = nt * 8 + tc * 2;
            uint32_t hp, lp;
            splitpair(oacc[nt][0] * il0, oacc[nt][1] * il0, hp, lp);
            *(uint32_t*)(oh + base0 + col) = hp;
            *(uint32_t*)(ol + base0 + col) = lp;
            splitpair(oacc[nt][2] * il1, oacc[nt][3] * il1, hp, lp);
            *(uint32_t*)(oh + base1 + col) = hp;
            *(uint32_t*)(ol + base1 + col) = lp;
        }
    }
}

// ---------------------------------------------------------------------------
// Launch
// ---------------------------------------------------------------------------
extern "C" void kernel_launch(void* const* d_in, const int* in_sizes, int n_in,
                              void* d_out, int out_size)
{
    const float* x_in  = (const float*)d_in[0];
    const int*   mask  = (const int*)  d_in[1];
    const float* ln1_g = (const float*)d_in[2];
    const float* ln1_b = (const float*)d_in[3];
    const float* qkv_w = (const float*)d_in[4];
    const float* out_w = (const float*)d_in[5];
    const float* out_b = (const float*)d_in[6];
    const float* ln2_g = (const float*)d_in[7];
    const float* ln2_b = (const float*)d_in[8];
    const float* ff1_w = (const float*)d_in[9];
    const float* ff1_b = (const float*)d_in[10];
    const float* ff2_w = (const float*)d_in[11];
    const float* ff2_b = (const float*)d_in[12];
    float* x = (float*)d_out;

    float* part;
    bf16 *qkvh, *qkvl, *hh, *hl, *h2h, *h2l, *oh, *ol;
    bf16 *wqh, *wql, *woh, *wol, *wf1h, *wf1l, *wf2h, *wf2l;
    cudaGetSymbolAddress((void**)&part, g_part);
    cudaGetSymbolAddress((void**)&qkvh, g_qkvh); cudaGetSymbolAddress((void**)&qkvl, g_qkvl);
    cudaGetSymbolAddress((void**)&hh,  g_hh);  cudaGetSymbolAddress((void**)&hl,  g_hl);
    cudaGetSymbolAddress((void**)&h2h, g_h2h); cudaGetSymbolAddress((void**)&h2l, g_h2l);
    cudaGetSymbolAddress((void**)&oh,  g_oh);  cudaGetSymbolAddress((void**)&ol,  g_ol);
    cudaGetSymbolAddress((void**)&wqh, g_wqkv_h); cudaGetSymbolAddress((void**)&wql, g_wqkv_l);
    cudaGetSymbolAddress((void**)&woh, g_wout_h); cudaGetSymbolAddress((void**)&wol, g_wout_l);
    cudaGetSymbolAddress((void**)&wf1h, g_wff1_h); cudaGetSymbolAddress((void**)&wf1l, g_wff1_l);
    cudaGetSymbolAddress((void**)&wf2h, g_wff2_h); cudaGetSymbolAddress((void**)&wf2l, g_wff2_l);

    cudaFuncSetAttribute(attn_kernel,
                         cudaFuncAttributeMaxDynamicSharedMemorySize, ATT_SMEM);
    cudaFuncSetAttribute(mma_gemm<0>,
                         cudaFuncAttributeMaxDynamicSharedMemorySize, GEMM_SMEM);
    cudaFuncSetAttribute(mma_gemm<2>,
                         cudaFuncAttributeMaxDynamicSharedMemorySize, GEMM_SMEM);
    cudaFuncSetAttribute(mma_gemm<3>,
                         cudaFuncAttributeMaxDynamicSharedMemorySize, GEMM_SMEM);

    cvt_kernel<<<4096, 256>>>(qkv_w, wqh, wql, DEPTH * DIMM * 3 * INNER / 4);
    cvt_kernel<<<2048, 256>>>(out_w, woh, wol, DEPTH * INNER * DIMM / 4);
    cvt_kernel<<<4096, 256>>>(ff1_w, wf1h, wf1l, DEPTH * DIMM * MLPD / 4);
    cvt_kernel<<<4096, 256>>>(ff2_w, wf2h, wf2l, DEPTH * MLPD * DIMM / 4);

    cudaMemcpyAsync(x, x_in, sizeof(float) * (size_t)TOK * DIMM,
                    cudaMemcpyDeviceToDevice);

    const int RED_N4 = TOK * DIMM / 4;

    for (int l = 0; l < DEPTH; ++l) {
        size_t wq = (size_t)l * DIMM * 3 * INNER;
        size_t wo = (size_t)l * INNER * DIMM;
        size_t w1 = (size_t)l * DIMM * MLPD;
        size_t w2 = (size_t)l * MLPD * DIMM;

        if (l == 0) {
            red_ln_kernel<0><<<TOK, 256>>>(x, nullptr, nullptr,
                                           ln1_g, ln1_b, hh, hl);
        } else {
            red_ln_kernel<4><<<TOK, 256>>>(x, ff2_b + (size_t)(l - 1) * DIMM,
                                           part,
                                           ln1_g + (size_t)l * DIMM,
                                           ln1_b + (size_t)l * DIMM, hh, hl);
        }
        mma_gemm<3><<<dim3(3 * INNER / 128, TOK / 128, 1), 256, GEMM_SMEM>>>(
            hh, hl, wqh + wq, wql + wq, nullptr, nullptr, qkvh, qkvl,
            TOK, 3 * INNER, DIMM, DIMM);
        attn_kernel<<<dim3(NN / 64, BB * HEADS), 128, ATT_SMEM>>>(
            qkvh, qkvl, mask, oh, ol);
        mma_gemm<0><<<dim3(DIMM / 128, TOK / 128, 2), 256, GEMM_SMEM>>>(
            oh, ol, woh + wo, wol + wo, part, nullptr, nullptr, nullptr,
            TOK, DIMM, INNER, INNER / 2);
        red_ln_kernel<2><<<TOK, 256>>>(x, out_b + (size_t)l * DIMM, part,
                                       ln2_g + (size_t)l * DIMM,
                                       ln2_b + (size_t)l * DIMM, hh, hl);
        mma_gemm<2><<<dim3(MLPD / 128, TOK / 128, 1), 256, GEMM_SMEM>>>(
            hh, hl, wf1h + w1, wf1l + w1, nullptr, ff1_b + (size_t)l * MLPD,
            h2h, h2l, TOK, MLPD, DIMM, DIMM);
        mma_gemm<0><<<dim3(DIMM / 128, TOK / 128, 4), 256, GEMM_SMEM>>>(
            h2h, h2l, wf2h + w2, wf2l + w2, part, nullptr, nullptr, nullptr,
            TOK, DIMM, MLPD, MLPD / 4);
    }
    reduce_kernel<4><<<RED_N4 / 256, 256>>>(x, ff2_b + (size_t)(DEPTH - 1) * DIMM,
                                            part, RED_N4);
}